// round 5
// baseline (speedup 1.0000x reference)
#include <cuda_runtime.h>
#include <math.h>

typedef unsigned long long u64;
#define BB 2
#define NN 512
#define DD 256
#define NH 4
#define MR (BB*NN)

__device__ float g_q[MR*DD];
__device__ float g_k[MR*DD];
__device__ float g_v[MR*DD];
__device__ float g_a[MR*DD];
__device__ float g_b[MR*DD];
__device__ __align__(16) float g_attn[(size_t)BB*NN*NN*NH];  // [b][i][j][h]
__device__ float g_ctx[MR*DD];

struct GCoef { float c[10]; };

__device__ __forceinline__ u64 pk(float lo, float hi) {
    u64 r; asm("mov.b64 %0,{%1,%2};" : "=l"(r) : "f"(lo), "f"(hi)); return r;
}
__device__ __forceinline__ void upk(u64 v, float& lo, float& hi) {
    asm("mov.b64 {%0,%1},%2;" : "=f"(lo), "=f"(hi) : "l"(v));
}
__device__ __forceinline__ u64 f2add(u64 a, u64 b) {
    u64 d; asm("add.rn.f32x2 %0,%1,%2;" : "=l"(d) : "l"(a), "l"(b)); return d;
}
__device__ __forceinline__ u64 f2fma(u64 a, u64 b, u64 c) {
    u64 d; asm("fma.rn.f32x2 %0,%1,%2,%3;" : "=l"(d) : "l"(a), "l"(b), "l"(c)); return d;
}

// ---- 16x64 GEMM, K=256, 128 threads, double-buffered w/ register prefetch ----
__device__ __forceinline__ void gemm16x64(
    const float* __restrict__ A, const float* __restrict__ W,
    const float* __restrict__ bias, float* __restrict__ C,
    int m0, int n0)
{
    __shared__ __align__(16) float As[2][16][20];
    __shared__ __align__(16) float Ws[2][16][68];
    int tid = threadIdx.x, tx = tid & 15, ty = tid >> 4;
    u64 acc[2][2] = {{0ull,0ull},{0ull,0ull}};

    bool aload = tid < 64;
    int am = tid >> 2, ak = (tid & 3) * 4;
    int wk0 = tid >> 4, wk1 = (tid + 128) >> 4, wn = (tid & 15) * 4;

    float4 pA = {}, pW0, pW1;
    if (aload) pA = *(const float4*)&A[(m0 + am) * 256 + ak];
    pW0 = *(const float4*)&W[wk0 * 256 + n0 + wn];
    pW1 = *(const float4*)&W[wk1 * 256 + n0 + wn];

    int buf = 0;
    #pragma unroll 4
    for (int t = 0; t < 16; t++) {
        if (aload) *(float4*)&As[buf][am][ak] = pA;
        *(float4*)&Ws[buf][wk0][wn] = pW0;
        *(float4*)&Ws[buf][wk1][wn] = pW1;
        __syncthreads();
        if (t < 15) {
            int k0 = (t + 1) * 16;
            if (aload) pA = *(const float4*)&A[(m0 + am) * 256 + k0 + ak];
            pW0 = *(const float4*)&W[(k0 + wk0) * 256 + n0 + wn];
            pW1 = *(const float4*)&W[(k0 + wk1) * 256 + n0 + wn];
        }
        #pragma unroll
        for (int kk = 0; kk < 16; kk++) {
            float ra0 = As[buf][ty * 2][kk], ra1 = As[buf][ty * 2 + 1][kk];
            ulonglong2 wv = *(const ulonglong2*)&Ws[buf][kk][tx * 4];
            u64 r0 = pk(ra0, ra0), r1 = pk(ra1, ra1);
            acc[0][0] = f2fma(r0, wv.x, acc[0][0]);
            acc[0][1] = f2fma(r0, wv.y, acc[0][1]);
            acc[1][0] = f2fma(r1, wv.x, acc[1][0]);
            acc[1][1] = f2fma(r1, wv.y, acc[1][1]);
        }
        buf ^= 1;
    }
    int n = n0 + tx * 4;
    float b0 = 0.f, b1 = 0.f, b2 = 0.f, b3 = 0.f;
    if (bias) { b0 = bias[n]; b1 = bias[n+1]; b2 = bias[n+2]; b3 = bias[n+3]; }
    #pragma unroll
    for (int i = 0; i < 2; i++) {
        float o0,o1,o2,o3;
        upk(acc[i][0], o0, o1); upk(acc[i][1], o2, o3);
        *(float4*)&C[(m0 + ty*2 + i) * 256 + n] =
            make_float4(o0 + b0, o1 + b1, o2 + b2, o3 + b3);
    }
}

__global__ __launch_bounds__(128) void k_proj(
    const float* __restrict__ x,
    const float* __restrict__ Wq, const float* __restrict__ bq,
    const float* __restrict__ Wk, const float* __restrict__ bk,
    const float* __restrict__ Wv, const float* __restrict__ bv,
    const float* __restrict__ Wp1, const float* __restrict__ bp1)
{
    int bn = blockIdx.x;
    int seg = bn >> 2, n0 = (bn & 3) * 64;
    const float* W; const float* bias; float* C;
    switch (seg) {
        case 0: W = Wq; bias = bq; C = g_q; break;
        case 1: W = Wk; bias = bk; C = g_k; break;
        case 2: W = Wv; bias = bv; C = g_v; break;
        case 3: W = Wp1; bias = nullptr; C = g_a; break;
        default: W = Wp1 + 256*256; bias = bp1; C = g_b; break;  // bp1 folded
    }
    gemm16x64(x, W, bias, C, blockIdx.y * 16, n0);
}

// ---------------- K2: fused pair scores ----------------
__global__ __launch_bounds__(256, 2) void k_scores(
    const int* __restrict__ adj, const float* __restrict__ Wp2,
    const float* __restrict__ bp2, GCoef co)
{
    int b = blockIdx.z, i0 = blockIdx.y * 8, j0base = blockIdx.x * 128;
    int tid = threadIdx.x, lane = tid & 31, w = tid >> 5;
    int h = lane >> 3;

    __shared__ __align__(16) float sA[8][256], sQ[8][256], sB[8][256], sK[8][256];
    __shared__ int sM[8][128];

    u64 C[10];
    #pragma unroll
    for (int kk = 0; kk < 10; kk++) C[kk] = pk(co.c[kk], co.c[kk]);
    const u64 K3 = pk(1.0f/3.0f, 1.0f/3.0f);
    const u64 KM1 = pk(-1.0f, -1.0f);
    const u64 KABS = 0x7FFFFFFF7FFFFFFFull;

    u64 w2[4][4];
    {
        int cb = lane * 8;
        #pragma unroll
        for (int p = 0; p < 4; p++) {
            float4 wa = *(const float4*)&Wp2[(cb + 2*p) * 4];
            float4 wb = *(const float4*)&Wp2[(cb + 2*p + 1) * 4];
            w2[p][0] = pk(0.5f*wa.x, 0.5f*wb.x);
            w2[p][1] = pk(0.5f*wa.y, 0.5f*wb.y);
            w2[p][2] = pk(0.5f*wa.z, 0.5f*wb.z);
            w2[p][3] = pk(0.5f*wa.w, 0.5f*wb.w);
        }
    }
    float myb = bp2[h];

    const float* aptr = g_a + (b * NN + i0) * 256;
    const float* qptr = g_q + (b * NN + i0) * 256;
    #pragma unroll
    for (int t = 0; t < 2; t++) {
        int idx = tid + t * 256;
        ((float4*)sA)[idx] = ((const float4*)aptr)[idx];
        ((float4*)sQ)[idx] = ((const float4*)qptr)[idx];
    }
    #pragma unroll
    for (int t = 0; t < 4; t++) {
        int idx = tid + t * 256;
        sM[idx >> 7][idx & 127] = adj[(i0 + (idx >> 7)) * NN + j0base + (idx & 127)];
    }

    for (int jc = 0; jc < 128; jc += 8) {
        int j0 = j0base + jc;
        __syncthreads();
        const float* bptr = g_b + (b * NN + j0) * 256;
        const float* kptr = g_k + (b * NN + j0) * 256;
        #pragma unroll
        for (int t = 0; t < 2; t++) {
            int idx = tid + t * 256;
            ((float4*)sB)[idx] = ((const float4*)bptr)[idx];
            ((float4*)sK)[idx] = ((const float4*)kptr)[idx];
        }
        __syncthreads();

        int j = j0 + w;
        u64 bbp[4], kvp[4];
        {
            ulonglong2 x0 = *(const ulonglong2*)&sB[w][lane*8];
            ulonglong2 x1 = *(const ulonglong2*)&sB[w][lane*8+4];
            bbp[0]=x0.x; bbp[1]=x0.y; bbp[2]=x1.x; bbp[3]=x1.y;
            ulonglong2 y0 = *(const ulonglong2*)&sK[w][lane*8];
            ulonglong2 y1 = *(const ulonglong2*)&sK[w][lane*8+4];
            kvp[0]=y0.x; kvp[1]=y0.y; kvp[2]=y1.x; kvp[3]=y1.y;
        }

        #pragma unroll
        for (int il = 0; il < 8; il++) {
            if (sM[il][jc + w] == 0) continue;     // masked: k_av zeroes it
            int i = i0 + il;
            u64 aA[4], qA[4];
            {
                ulonglong2 x0 = *(const ulonglong2*)&sA[il][lane*8];
                ulonglong2 x1 = *(const ulonglong2*)&sA[il][lane*8+4];
                aA[0]=x0.x; aA[1]=x0.y; aA[2]=x1.x; aA[3]=x1.y;
                ulonglong2 y0 = *(const ulonglong2*)&sQ[il][lane*8];
                ulonglong2 y1 = *(const ulonglong2*)&sQ[il][lane*8+4];
                qA[0]=y0.x; qA[1]=y0.y; qA[2]=y1.x; qA[3]=y1.y;
            }
            u64 aw0=0, aw1=0, aw2=0, aw3=0, qk=0;
            #pragma unroll
            for (int p = 0; p < 4; p++) {
                u64 t = f2add(aA[p], bbp[p]);
                u64 m = t & KABS;
                u64 wv = f2fma(m, K3, KM1);
                u64 S = C[9];
                #pragma unroll
                for (int kk = 8; kk >= 0; kk--) S = f2fma(S, wv, C[kk]);
                u64 G = f2add(f2add(t, m), S);   // 2*gelu
                aw0 = f2fma(G, w2[p][0], aw0);
                aw1 = f2fma(G, w2[p][1], aw1);
                aw2 = f2fma(G, w2[p][2], aw2);
                aw3 = f2fma(G, w2[p][3], aw3);
                qk  = f2fma(qA[p], kvp[p], qk);
            }
            float r0,r1,r2,r3,x0,x1,qx,qy;
            upk(aw0,r0,x0); r0+=x0;
            upk(aw1,r1,x1); r1+=x1;
            upk(aw2,r2,x0); r2+=x0;
            upk(aw3,r3,x1); r3+=x1;
            upk(qk,qx,qy);
            float qs = (qx+qy)*0.125f;
            if (h==0) r0+=qs; else if (h==1) r1+=qs; else if (h==2) r2+=qs; else r3+=qs;

            r0 += __shfl_xor_sync(~0u, r0, 16);
            r1 += __shfl_xor_sync(~0u, r1, 16);
            r2 += __shfl_xor_sync(~0u, r2, 16);
            r3 += __shfl_xor_sync(~0u, r3, 16);
            r0 += __shfl_xor_sync(~0u, r0, 8);
            r1 += __shfl_xor_sync(~0u, r1, 8);
            r2 += __shfl_xor_sync(~0u, r2, 8);
            r3 += __shfl_xor_sync(~0u, r3, 8);
            float v = (h==0)?r0:(h==1)?r1:(h==2)?r2:r3;
            v += __shfl_xor_sync(~0u, v, 4);
            v += __shfl_xor_sync(~0u, v, 2);
            v += __shfl_xor_sync(~0u, v, 1);
            if ((lane & 7) == 0)
                g_attn[(((size_t)b*NN + i)*NN + j)*NH + h] = v + myb;
        }
    }
}

// ---------------- fast exp (no MUFU) ----------------
__device__ __forceinline__ float fexp(float x) {
    x = fmaxf(x, -87.0f);
    float y = x * 1.4426950408889634f;
    float f = floorf(y);
    float r = y - f;
    float p = 1.5403530e-4f;
    p = fmaf(p, r, 1.3333558e-3f);
    p = fmaf(p, r, 9.6181291e-3f);
    p = fmaf(p, r, 5.5504109e-2f);
    p = fmaf(p, r, 2.4022651e-1f);
    p = fmaf(p, r, 6.9314718e-1f);
    p = fmaf(p, r, 1.0f);
    return __int_as_float(__float_as_int(p) + (((int)f) << 23));
}

// ---------------- K3: fused mask+softmax+attn@v;  grid (64 i-tiles, 2 hp, 2 b) ----------------
__global__ __launch_bounds__(256) void k_av(const int* __restrict__ adj)
{
    int b = blockIdx.z, hp = blockIdx.y, i0 = blockIdx.x * 8;
    int tid = threadIdx.x, w = tid >> 5, lane = tid & 31;

    __shared__ float sP[8][2][520];            // 33.3 KB
    __shared__ float sRed[2][8][2][64];        //  8 KB
    __shared__ float sInv[8][2];

    // phase A: warp w = row i0+w; both heads of pair hp at once (float2 loads)
    {
        int i = i0 + w;
        const float2* ap = (const float2*)(g_attn + (((size_t)b*NN + i)*NN)*NH + hp*2);
        const int* mrow = adj + i * NN;
        float2 av[16]; unsigned mb = 0;
        #pragma unroll
        for (int t = 0; t < 16; t++) {
            int j = lane + 32 * t;
            av[t] = ap[(size_t)j * 2];
            if (mrow[j]) mb |= 1u << t;
        }
        float mx0 = -3.4e38f, mx1 = -3.4e38f;
        #pragma unroll
        for (int t = 0; t < 16; t++)
            if ((mb >> t) & 1) { mx0 = fmaxf(mx0, av[t].x); mx1 = fmaxf(mx1, av[t].y); }
        #pragma unroll
        for (int o = 16; o; o >>= 1) {
            mx0 = fmaxf(mx0, __shfl_xor_sync(~0u, mx0, o));
            mx1 = fmaxf(mx1, __shfl_xor_sync(~0u, mx1, o));
        }
        float s0 = 0.f, s1 = 0.f;
        #pragma unroll
        for (int t = 0; t < 16; t++) {
            bool ok = (mb >> t) & 1;
            float p0 = ok ? fexp(av[t].x - mx0) : 0.f;
            float p1 = ok ? fexp(av[t].y - mx1) : 0.f;
            int j = lane + 32 * t;
            sP[w][0][j] = p0; sP[w][1][j] = p1;
            s0 += p0; s1 += p1;
        }
        #pragma unroll
        for (int o = 16; o; o >>= 1) {
            s0 += __shfl_xor_sync(~0u, s0, o);
            s1 += __shfl_xor_sync(~0u, s1, o);
        }
        if (lane == 0) { sInv[w][0] = 1.0f / s0; sInv[w][1] = 1.0f / s1; }
    }
    __syncthreads();

    // phase B: warp w -> (h = w&1, dhalf = (w>>1)&1, jhalf = w>>2)
    {
        int h = w & 1, dh = (w >> 1) & 1, jh = w >> 2;
        int d = dh * 32 + lane;
        const float* vp = &g_v[((size_t)b*NN + jh*256)*256 + (hp*2 + h)*64 + d];
        float acc[8] = {};
        #pragma unroll 2
        for (int jj = 0; jj < 256; jj++) {
            float vv = vp[(size_t)jj * 256];
            int j = jh * 256 + jj;
            #pragma unroll
            for (int i = 0; i < 8; i++)
                acc[i] = fmaf(sP[i][h][j], vv, acc[i]);
        }
        #pragma unroll
        for (int i = 0; i < 8; i++) sRed[jh][i][h][d] = acc[i];
    }
    __syncthreads();

    // phase C: 1024 outputs (8 rows x 2 heads x 64 d), 4 per thread
    #pragma unroll
    for (int e = tid; e < 1024; e += 256) {
        int d = e & 63, h = (e >> 6) & 1, i = e >> 7;
        float v = sRed[0][i][h][d] + sRed[1][i][h][d];
        g_ctx[((size_t)b*NN + i0 + i)*256 + (hp*2 + h)*64 + d] = v * sInv[i][h];
    }
}

__global__ __launch_bounds__(128) void k_out(
    const float* __restrict__ Wo, const float* __restrict__ bo,
    float* __restrict__ out)
{
    gemm16x64(g_ctx, Wo, bo, out, blockIdx.y * 16, blockIdx.x * 64);
}

// ---- host: Chebyshev fit of -2*0.5*m*erfc(m/sqrt2)*... (S(m) = -m*erfc(m/sqrt2)), m in [0,6], deg 9 ----
static GCoef fit_gelu_poly() {
    const int DEG = 9, M = 64;
    double cc[DEG+1], fv[M];
    for (int j = 0; j < M; j++) {
        double xx = cos(M_PI * (j + 0.5) / M);
        double m = 3.0 * (xx + 1.0);
        fv[j] = -m * erfc(m * 0.7071067811865476);
    }
    for (int k = 0; k <= DEG; k++) {
        double s = 0;
        for (int j = 0; j < M; j++) s += fv[j] * cos(k * M_PI * (j + 0.5) / M);
        cc[k] = s * ((k == 0 ? 1.0 : 2.0) / M);
    }
    double mono[DEG+1] = {0}, Tm2[DEG+1] = {0}, Tm1[DEG+1] = {0}, Tk[DEG+1];
    Tm2[0] = 1.0; Tm1[1] = 1.0;
    mono[0] += cc[0];
    mono[1] += cc[1];
    for (int k = 2; k <= DEG; k++) {
        for (int i = 0; i <= DEG; i++) Tk[i] = -Tm2[i] + 2.0 * (i > 0 ? Tm1[i-1] : 0.0);
        for (int i = 0; i <= DEG; i++) mono[i] += cc[k] * Tk[i];
        for (int i = 0; i <= DEG; i++) { Tm2[i] = Tm1[i]; Tm1[i] = Tk[i]; }
    }
    GCoef g;
    for (int i = 0; i <= DEG; i++) g.c[i] = (float)mono[i];
    return g;
}

extern "C" void kernel_launch(void* const* d_in, const int* in_sizes, int n_in,
                              void* d_out, int out_size)
{
    const float* x   = (const float*)d_in[0];
    const int*   adj = (const int*)  d_in[1];
    const float* Wq  = (const float*)d_in[2];
    const float* bq  = (const float*)d_in[3];
    const float* Wk  = (const float*)d_in[4];
    const float* bk  = (const float*)d_in[5];
    const float* Wv  = (const float*)d_in[6];
    const float* bv  = (const float*)d_in[7];
    const float* Wo  = (const float*)d_in[8];
    const float* bo  = (const float*)d_in[9];
    const float* Wp1 = (const float*)d_in[10];
    const float* bp1 = (const float*)d_in[11];
    const float* Wp2 = (const float*)d_in[12];
    const float* bp2 = (const float*)d_in[13];
    float* out = (float*)d_out;

    GCoef co = fit_gelu_poly();

    dim3 g1(20, 64);
    k_proj<<<g1, 128>>>(x, Wq, bq, Wk, bk, Wv, bv, Wp1, bp1);

    dim3 g2(4, 64, 2);
    k_scores<<<g2, 256>>>(adj, Wp2, bp2, co);

    dim3 g4(64, 2, 2);
    k_av<<<g4, 256>>>(adj);

    dim3 g5(4, 64);
    k_out<<<g5, 128>>>(Wo, bo, out);
}